// round 3
// baseline (speedup 1.0000x reference)
#include <cuda_runtime.h>
#include <cuda_bf16.h>

// ROI bilinear pooling (TF2 half_pixel_centers resize semantics).
// img: [1, 100, 100, 512] f32 NHWC ; rois: [1, 300, 4] int32 (x, y, w, h)
// out: [1, 300, 14, 14, 512] f32
//
// One block per output pixel (roi, py, px); 128 threads x float4 = 512 channels.
// All global traffic is coalesced 2KB rows; img is L2-resident (20.5 MB < 126 MB L2).

#define POOL 14
#define NUM_ROIS 300
#define FM_H 100
#define FM_W 100
#define FM_C 512

__global__ __launch_bounds__(128, 16)
void roi_pool_kernel(const float* __restrict__ img,
                     const int*   __restrict__ rois,
                     float*       __restrict__ out)
{
    const int b  = blockIdx.x;              // 0 .. 300*14*14-1
    const int r  = b / (POOL * POOL);
    const int pr = b - r * (POOL * POOL);
    const int py = pr / POOL;
    const int px = pr - py * POOL;

    // rois layout: [300][4] = x, y, w, h
    const int4 roi = __ldg(((const int4*)rois) + r);
    const int rx = roi.x, ry = roi.y, rw = roi.z, rh = roi.w;

    // x axis coords (half-pixel centers)
    float srcx = (px + 0.5f) * ((float)rw / (float)POOL) - 0.5f;
    float fx   = floorf(srcx);
    float tx   = srcx - fx;
    int   fxi  = (int)fx;
    int   xlo  = min(max(fxi,     0), rw - 1) + rx;
    int   xhi  = min(max(fxi + 1, 0), rw - 1) + rx;

    // y axis coords
    float srcy = (py + 0.5f) * ((float)rh / (float)POOL) - 0.5f;
    float fy   = floorf(srcy);
    float ty   = srcy - fy;
    int   fyi  = (int)fy;
    int   ylo  = min(max(fyi,     0), rh - 1) + ry;
    int   yhi  = min(max(fyi + 1, 0), rh - 1) + ry;

    const float w00 = (1.0f - ty) * (1.0f - tx);
    const float w01 = (1.0f - ty) * tx;
    const float w10 = ty * (1.0f - tx);
    const float w11 = ty * tx;

    // channel offset for this thread (float4 granularity)
    const int c4 = threadIdx.x;             // 0..127
    const size_t row_ll = ((size_t)ylo * FM_W + xlo) * (FM_C / 4);
    const size_t row_lh = ((size_t)ylo * FM_W + xhi) * (FM_C / 4);
    const size_t row_hl = ((size_t)yhi * FM_W + xlo) * (FM_C / 4);
    const size_t row_hh = ((size_t)yhi * FM_W + xhi) * (FM_C / 4);

    const float4* img4 = (const float4*)img;
    const float4 a  = __ldg(img4 + row_ll + c4);
    const float4 bq = __ldg(img4 + row_lh + c4);
    const float4 c  = __ldg(img4 + row_hl + c4);
    const float4 d  = __ldg(img4 + row_hh + c4);

    float4 o;
    o.x = w00 * a.x + w01 * bq.x + w10 * c.x + w11 * d.x;
    o.y = w00 * a.y + w01 * bq.y + w10 * c.y + w11 * d.y;
    o.z = w00 * a.z + w01 * bq.z + w10 * c.z + w11 * d.z;
    o.w = w00 * a.w + w01 * bq.w + w10 * c.w + w11 * d.w;

    float4* out4 = (float4*)out;
    out4[(size_t)b * (FM_C / 4) + c4] = o;
}

extern "C" void kernel_launch(void* const* d_in, const int* in_sizes, int n_in,
                              void* d_out, int out_size)
{
    // Resolve inputs by size, not position: img = 1*100*100*512 = 5,120,000
    // elements; rois = 1*300*4 = 1,200 elements.
    const float* img;
    const int*   rois;
    if (in_sizes[0] > in_sizes[1]) {
        img  = (const float*)d_in[0];
        rois = (const int*)d_in[1];
    } else {
        img  = (const float*)d_in[1];
        rois = (const int*)d_in[0];
    }
    float* out = (float*)d_out;

    const int blocks = NUM_ROIS * POOL * POOL;   // 58800
    roi_pool_kernel<<<blocks, 128>>>(img, rois, out);
}

// round 4
// speedup vs baseline: 1.0547x; 1.0547x over previous
#include <cuda_runtime.h>
#include <cuda_bf16.h>

// ROI bilinear pooling (TF2 half_pixel_centers resize semantics).
// img: [1, 100, 100, 512] f32 NHWC ; rois: [1, 300, 4] int32 (x, y, w, h)
// out: [1, 300, 14, 14, 512] f32
//
// R3: block = (roi, py). 128 threads x float4 = 512 channels; loop over the 14
// px positions. Y-axis math + ROI load amortized over the loop; per-iteration
// instruction count ~35/warp vs ~80 before, putting issue well under the L1
// wavefront floor (20 wf per warp-pixel). Output written with __stcs to keep
// L2 priority on the reused image lines.

#define POOL 14
#define NUM_ROIS 300
#define FM_H 100
#define FM_W 100
#define FM_C 512
#define C4 (FM_C / 4)          // 128 float4 per pixel row

__global__ __launch_bounds__(128, 16)
void roi_pool_kernel(const float4* __restrict__ img4,
                     const int*    __restrict__ rois,
                     float4*       __restrict__ out4)
{
    const int b  = blockIdx.x;          // 0 .. 300*14-1
    const int r  = b / POOL;
    const int py = b - r * POOL;
    const int c4 = threadIdx.x;         // 0..127 channel group

    // rois layout: [300][4] = x, y, w, h
    const int4 roi = __ldg(((const int4*)rois) + r);
    const int rx = roi.x, ry = roi.y, rw = roi.z, rh = roi.w;

    // ---- y axis (once per block) ----
    const float srcy = (py + 0.5f) * ((float)rh * (1.0f / POOL)) - 0.5f;
    const float fy   = floorf(srcy);
    const float ty   = srcy - fy;
    const int   fyi  = (int)fy;
    const int   ylo  = min(max(fyi,     0), rh - 1) + ry;
    const int   yhi  = min(max(fyi + 1, 0), rh - 1) + ry;
    const float wy0  = 1.0f - ty;
    const float wy1  = ty;

    const int rowlo = ylo * (FM_W * C4);       // float4 index of row start
    const int rowhi = yhi * (FM_W * C4);

    const float sx = (float)rw * (1.0f / POOL);

    // output pointer for this (r, py, c4); consecutive px stride = C4 float4
    float4* optr = out4 + (size_t)(r * (POOL * POOL) + py * POOL) * C4 + c4;

    #pragma unroll 2
    for (int px = 0; px < POOL; ++px) {
        // ---- x axis ----
        const float srcx = (px + 0.5f) * sx - 0.5f;
        const float fx   = floorf(srcx);
        const float tx   = srcx - fx;
        const int   fxi  = (int)fx;
        const int   xlo  = min(max(fxi,     0), rw - 1) + rx;
        const int   xhi  = min(max(fxi + 1, 0), rw - 1) + rx;

        const float4 a  = __ldg(img4 + rowlo + xlo * C4 + c4);
        const float4 bq = __ldg(img4 + rowlo + xhi * C4 + c4);
        const float4 c  = __ldg(img4 + rowhi + xlo * C4 + c4);
        const float4 d  = __ldg(img4 + rowhi + xhi * C4 + c4);

        const float wx1 = tx;
        const float wx0 = 1.0f - tx;
        const float w00 = wy0 * wx0;
        const float w01 = wy0 * wx1;
        const float w10 = wy1 * wx0;
        const float w11 = wy1 * wx1;

        float4 o;
        o.x = w00 * a.x + w01 * bq.x + w10 * c.x + w11 * d.x;
        o.y = w00 * a.y + w01 * bq.y + w10 * c.y + w11 * d.y;
        o.z = w00 * a.z + w01 * bq.z + w10 * c.z + w11 * d.z;
        o.w = w00 * a.w + w01 * bq.w + w10 * c.w + w11 * d.w;

        __stcs(optr + px * C4, o);   // streaming store: output never re-read
    }
}

extern "C" void kernel_launch(void* const* d_in, const int* in_sizes, int n_in,
                              void* d_out, int out_size)
{
    // Resolve inputs by size, not position: img = 5,120,000 elems; rois = 1,200.
    const float* img;
    const int*   rois;
    if (in_sizes[0] > in_sizes[1]) {
        img  = (const float*)d_in[0];
        rois = (const int*)d_in[1];
    } else {
        img  = (const float*)d_in[1];
        rois = (const int*)d_in[0];
    }
    float* out = (float*)d_out;

    const int blocks = NUM_ROIS * POOL;   // 4200 blocks, one per (roi, row)
    roi_pool_kernel<<<blocks, 128>>>((const float4*)img, rois, (float4*)out);
}

// round 6
// speedup vs baseline: 1.0556x; 1.0009x over previous
#include <cuda_runtime.h>
#include <cuda_bf16.h>

// ROI bilinear pooling (TF2 half_pixel_centers resize semantics).
// img: [1, 100, 100, 512] f32 NHWC ; rois: [1, 300, 4] int32 (x, y, w, h)
// out: [1, 300, 14, 14, 512] f32
//
// R5 (= R4 resubmit; prior run was an infra failure): block = (roi, py).
// Per-px gather offsets (int4) + bilinear weights (float4) precomputed into
// smem by threads 0..13 (one barrier); 14-px loop fully unrolled with a body
// of 2 broadcast LDS.128 + 4 LDG.128 + 16 FFMA + STG.128 — no ALU in front of
// the loads, deep cross-iteration load batching. launch_bounds(128,8) gives
// ptxas 64 regs to software-pipeline.

#define POOL 14
#define NUM_ROIS 300
#define FM_H 100
#define FM_W 100
#define FM_C 512
#define C4 (FM_C / 4)          // 128 float4 per pixel row

__global__ __launch_bounds__(128, 8)
void roi_pool_kernel(const float4* __restrict__ img4,
                     const int*    __restrict__ rois,
                     float4*       __restrict__ out4)
{
    __shared__ int4   s_off[POOL];   // float4-element offsets of the 4 gather rows
    __shared__ float4 s_w[POOL];     // bilinear weights w00,w01,w10,w11

    const int b  = blockIdx.x;          // 0 .. 300*14-1
    const int r  = b / POOL;
    const int py = b - r * POOL;
    const int c4 = threadIdx.x;         // 0..127 channel group

    if (threadIdx.x < POOL) {
        const int px = threadIdx.x;

        // rois layout: [300][4] = x, y, w, h
        const int4 roi = __ldg(((const int4*)rois) + r);
        const int rx = roi.x, ry = roi.y, rw = roi.z, rh = roi.w;

        // ---- y axis ----
        const float srcy = (py + 0.5f) * ((float)rh * (1.0f / POOL)) - 0.5f;
        const float fy   = floorf(srcy);
        const float ty   = srcy - fy;
        const int   fyi  = (int)fy;
        const int   ylo  = min(max(fyi,     0), rh - 1) + ry;
        const int   yhi  = min(max(fyi + 1, 0), rh - 1) + ry;

        // ---- x axis ----
        const float srcx = (px + 0.5f) * ((float)rw * (1.0f / POOL)) - 0.5f;
        const float fx   = floorf(srcx);
        const float tx   = srcx - fx;
        const int   fxi  = (int)fx;
        const int   xlo  = min(max(fxi,     0), rw - 1) + rx;
        const int   xhi  = min(max(fxi + 1, 0), rw - 1) + rx;

        const int rowlo = ylo * (FM_W * C4);
        const int rowhi = yhi * (FM_W * C4);

        int4 off;
        off.x = rowlo + xlo * C4;   // a  (ylo, xlo)
        off.y = rowlo + xhi * C4;   // b  (ylo, xhi)
        off.z = rowhi + xlo * C4;   // c  (yhi, xlo)
        off.w = rowhi + xhi * C4;   // d  (yhi, xhi)
        s_off[px] = off;

        const float wy0 = 1.0f - ty, wy1 = ty;
        const float wx0 = 1.0f - tx, wx1 = tx;
        float4 w;
        w.x = wy0 * wx0;
        w.y = wy0 * wx1;
        w.z = wy1 * wx0;
        w.w = wy1 * wx1;
        s_w[px] = w;
    }
    __syncthreads();

    // output base for this (r, py): b = r*POOL + py, so out pixel base is b*POOL
    float4* optr = out4 + (size_t)b * (POOL * C4) + c4;

    #pragma unroll
    for (int px = 0; px < POOL; ++px) {
        const int4   off = s_off[px];   // broadcast LDS.128
        const float4 w   = s_w[px];     // broadcast LDS.128

        const float4 a  = __ldg(img4 + off.x + c4);
        const float4 bq = __ldg(img4 + off.y + c4);
        const float4 c  = __ldg(img4 + off.z + c4);
        const float4 d  = __ldg(img4 + off.w + c4);

        float4 o;
        o.x = w.x * a.x + w.y * bq.x + w.z * c.x + w.w * d.x;
        o.y = w.x * a.y + w.y * bq.y + w.z * c.y + w.w * d.y;
        o.z = w.x * a.z + w.y * bq.z + w.z * c.z + w.w * d.z;
        o.w = w.x * a.w + w.y * bq.w + w.z * c.w + w.w * d.w;

        __stcs(optr + px * C4, o);   // streaming store: output never re-read
    }
}

extern "C" void kernel_launch(void* const* d_in, const int* in_sizes, int n_in,
                              void* d_out, int out_size)
{
    // Resolve inputs by size, not position: img = 5,120,000 elems; rois = 1,200.
    const float* img;
    const int*   rois;
    if (in_sizes[0] > in_sizes[1]) {
        img  = (const float*)d_in[0];
        rois = (const int*)d_in[1];
    } else {
        img  = (const float*)d_in[1];
        rois = (const int*)d_in[0];
    }
    float* out = (float*)d_out;

    const int blocks = NUM_ROIS * POOL;   // 4200 blocks, one per (roi, row)
    roi_pool_kernel<<<blocks, 128>>>((const float4*)img, rois, (float4*)out);
}

// round 7
// speedup vs baseline: 1.0639x; 1.0079x over previous
#include <cuda_runtime.h>
#include <cuda_bf16.h>

// ROI bilinear pooling (TF2 half_pixel_centers resize semantics).
// img: [1, 100, 100, 512] f32 NHWC ; rois: [1, 300, 4] int32 (x, y, w, h)
// out: [1, 300, 14, 14, 512] f32
//
// R6: persistent CTAs. grid = 148 SM x 8 = 1184 blocks; each block loops over
// ~4 (roi, py) work items (4200 total). Per-item gather offsets + bilinear
// weights are precomputed into a DOUBLE-BUFFERED smem slot by threads 0..13,
// one __syncthreads per item; the 14-px loop is fully unrolled (4x LDG.128 +
// 16 FFMA + STG.128 per px). This removes wave transitions and the 45%-empty
// tail wave of the 4200-block launch, and overlaps item i+1's coord math with
// item i's memory loop.

#define POOL 14
#define NUM_ROIS 300
#define FM_H 100
#define FM_W 100
#define FM_C 512
#define C4 (FM_C / 4)            // 128 float4 per pixel row
#define NUM_ITEMS (NUM_ROIS * POOL)   // 4200
#define NUM_SMS 148
#define BLOCKS_PER_SM 8
#define GRID_BLOCKS (NUM_SMS * BLOCKS_PER_SM)   // 1184

__global__ __launch_bounds__(128, BLOCKS_PER_SM)
void roi_pool_kernel(const float4* __restrict__ img4,
                     const int*    __restrict__ rois,
                     float4*       __restrict__ out4)
{
    __shared__ int4   s_off[2][POOL];  // double-buffered gather offsets
    __shared__ float4 s_w[2][POOL];    // double-buffered bilinear weights

    const int c4  = threadIdx.x;       // 0..127 channel group
    const int tid = threadIdx.x;

    int stage = 0;
    for (int item = blockIdx.x; item < NUM_ITEMS; item += GRID_BLOCKS, stage ^= 1) {
        // ---- precompute this item's coords into smem (threads 0..13) ----
        if (tid < POOL) {
            const int px = tid;
            const int r  = item / POOL;
            const int py = item - r * POOL;

            const int4 roi = __ldg(((const int4*)rois) + r);
            const int rx = roi.x, ry = roi.y, rw = roi.z, rh = roi.w;

            // y axis (half-pixel centers)
            const float srcy = (py + 0.5f) * ((float)rh * (1.0f / POOL)) - 0.5f;
            const float fy   = floorf(srcy);
            const float ty   = srcy - fy;
            const int   fyi  = (int)fy;
            const int   ylo  = min(max(fyi,     0), rh - 1) + ry;
            const int   yhi  = min(max(fyi + 1, 0), rh - 1) + ry;

            // x axis
            const float srcx = (px + 0.5f) * ((float)rw * (1.0f / POOL)) - 0.5f;
            const float fx   = floorf(srcx);
            const float tx   = srcx - fx;
            const int   fxi  = (int)fx;
            const int   xlo  = min(max(fxi,     0), rw - 1) + rx;
            const int   xhi  = min(max(fxi + 1, 0), rw - 1) + rx;

            const int rowlo = ylo * (FM_W * C4);
            const int rowhi = yhi * (FM_W * C4);

            int4 off;
            off.x = rowlo + xlo * C4;   // (ylo, xlo)
            off.y = rowlo + xhi * C4;   // (ylo, xhi)
            off.z = rowhi + xlo * C4;   // (yhi, xlo)
            off.w = rowhi + xhi * C4;   // (yhi, xhi)
            s_off[stage][px] = off;

            const float wy0 = 1.0f - ty, wy1 = ty;
            const float wx0 = 1.0f - tx, wx1 = tx;
            float4 w;
            w.x = wy0 * wx0;
            w.y = wy0 * wx1;
            w.z = wy1 * wx0;
            w.w = wy1 * wx1;
            s_w[stage][px] = w;
        }
        __syncthreads();   // coords visible; prev item's buffer (other stage) now free

        // ---- memory loop: 14 px, fully unrolled ----
        float4* optr = out4 + (size_t)item * (POOL * C4) + c4;

        #pragma unroll
        for (int px = 0; px < POOL; ++px) {
            const int4   off = s_off[stage][px];   // broadcast LDS.128
            const float4 w   = s_w[stage][px];     // broadcast LDS.128

            const float4 a  = __ldg(img4 + off.x + c4);
            const float4 bq = __ldg(img4 + off.y + c4);
            const float4 c  = __ldg(img4 + off.z + c4);
            const float4 d  = __ldg(img4 + off.w + c4);

            float4 o;
            o.x = w.x * a.x + w.y * bq.x + w.z * c.x + w.w * d.x;
            o.y = w.x * a.y + w.y * bq.y + w.z * c.y + w.w * d.y;
            o.z = w.x * a.z + w.y * bq.z + w.z * c.z + w.w * d.z;
            o.w = w.x * a.w + w.y * bq.w + w.z * c.w + w.w * d.w;

            __stcs(optr + px * C4, o);   // streaming store: output never re-read
        }
        // no trailing barrier: next iteration writes the OTHER smem stage
    }
}

extern "C" void kernel_launch(void* const* d_in, const int* in_sizes, int n_in,
                              void* d_out, int out_size)
{
    // Resolve inputs by size, not position: img = 5,120,000 elems; rois = 1,200.
    const float* img;
    const int*   rois;
    if (in_sizes[0] > in_sizes[1]) {
        img  = (const float*)d_in[0];
        rois = (const int*)d_in[1];
    } else {
        img  = (const float*)d_in[1];
        rois = (const int*)d_in[0];
    }
    float* out = (float*)d_out;

    roi_pool_kernel<<<GRID_BLOCKS, 128>>>((const float4*)img, rois, (float4*)out);
}

// round 9
// speedup vs baseline: 1.0966x; 1.0307x over previous
#include <cuda_runtime.h>
#include <cuda_bf16.h>

// ROI bilinear pooling (TF2 half_pixel_centers resize semantics).
// img: [1, 100, 100, 512] f32 NHWC ; rois: [1, 300, 4] int32 (x, y, w, h)
// out: [1, 300, 14, 14, 512] f32
//
// R8 (= R7 resubmit; prior run was an infra failure): persistent-CTA structure,
// ALL global accesses 64-bit (LDG.64/STG.64) at warp-contiguous addresses.
// LDG.128 = 4 within-instruction wavefronts (~2.07 cyc/wf); LDG.64 = 2, and
// wavefronts of different instructions pipeline at ~1.0 cyc/wf. Same bytes,
// same coalescing, ~40% less L1tex occupancy per warp-pixel. Thread t covers
// float2 chunks t and t+128 of each 2KB pixel row.

#define POOL 14
#define NUM_ROIS 300
#define FM_H 100
#define FM_W 100
#define FM_C 512
#define C2 (FM_C / 2)            // 256 float2 per pixel row
#define NUM_ITEMS (NUM_ROIS * POOL)   // 4200
#define NUM_SMS 148
#define BLOCKS_PER_SM 8
#define GRID_BLOCKS (NUM_SMS * BLOCKS_PER_SM)   // 1184

__global__ __launch_bounds__(128, BLOCKS_PER_SM)
void roi_pool_kernel(const float2* __restrict__ img2,
                     const int*    __restrict__ rois,
                     float2*       __restrict__ out2)
{
    __shared__ int4   s_off[2][POOL];  // float2-element offsets of the 4 gather rows
    __shared__ float4 s_w[2][POOL];    // bilinear weights w00,w01,w10,w11

    const int t = threadIdx.x;         // 0..127 : float2 chunks t and t+128

    int stage = 0;
    for (int item = blockIdx.x; item < NUM_ITEMS; item += GRID_BLOCKS, stage ^= 1) {
        // ---- precompute this item's coords into smem (threads 0..13) ----
        if (t < POOL) {
            const int px = t;
            const int r  = item / POOL;
            const int py = item - r * POOL;

            const int4 roi = __ldg(((const int4*)rois) + r);
            const int rx = roi.x, ry = roi.y, rw = roi.z, rh = roi.w;

            // y axis (half-pixel centers)
            const float srcy = (py + 0.5f) * ((float)rh * (1.0f / POOL)) - 0.5f;
            const float fy   = floorf(srcy);
            const float ty   = srcy - fy;
            const int   fyi  = (int)fy;
            const int   ylo  = min(max(fyi,     0), rh - 1) + ry;
            const int   yhi  = min(max(fyi + 1, 0), rh - 1) + ry;

            // x axis
            const float srcx = (px + 0.5f) * ((float)rw * (1.0f / POOL)) - 0.5f;
            const float fx   = floorf(srcx);
            const float tx   = srcx - fx;
            const int   fxi  = (int)fx;
            const int   xlo  = min(max(fxi,     0), rw - 1) + rx;
            const int   xhi  = min(max(fxi + 1, 0), rw - 1) + rx;

            const int rowlo = ylo * (FM_W * C2);   // float2 index of row start
            const int rowhi = yhi * (FM_W * C2);

            int4 off;
            off.x = rowlo + xlo * C2;   // (ylo, xlo)
            off.y = rowlo + xhi * C2;   // (ylo, xhi)
            off.z = rowhi + xlo * C2;   // (yhi, xlo)
            off.w = rowhi + xhi * C2;   // (yhi, xhi)
            s_off[stage][px] = off;

            const float wy0 = 1.0f - ty, wy1 = ty;
            const float wx0 = 1.0f - tx, wx1 = tx;
            float4 w;
            w.x = wy0 * wx0;
            w.y = wy0 * wx1;
            w.z = wy1 * wx0;
            w.w = wy1 * wx1;
            s_w[stage][px] = w;
        }
        __syncthreads();   // coords visible; other stage free for next item

        // ---- memory loop: 14 px, fully unrolled, all 64-bit accesses ----
        float2* optr = out2 + (size_t)item * (POOL * C2) + t;

        #pragma unroll
        for (int px = 0; px < POOL; ++px) {
            const int4   off = s_off[stage][px];   // broadcast LDS.128
            const float4 w   = s_w[stage][px];     // broadcast LDS.128

            // chunk 0: float2 index t ; chunk 1: float2 index t+128
            const float2 a0 = __ldg(img2 + off.x + t);
            const float2 b0 = __ldg(img2 + off.y + t);
            const float2 c0 = __ldg(img2 + off.z + t);
            const float2 d0 = __ldg(img2 + off.w + t);
            const float2 a1 = __ldg(img2 + off.x + t + 128);
            const float2 b1 = __ldg(img2 + off.y + t + 128);
            const float2 c1 = __ldg(img2 + off.z + t + 128);
            const float2 d1 = __ldg(img2 + off.w + t + 128);

            float2 o0, o1;
            o0.x = w.x * a0.x + w.y * b0.x + w.z * c0.x + w.w * d0.x;
            o0.y = w.x * a0.y + w.y * b0.y + w.z * c0.y + w.w * d0.y;
            o1.x = w.x * a1.x + w.y * b1.x + w.z * c1.x + w.w * d1.x;
            o1.y = w.x * a1.y + w.y * b1.y + w.z * c1.y + w.w * d1.y;

            __stcs(optr + px * C2,       o0);   // streaming stores, 64-bit
            __stcs(optr + px * C2 + 128, o1);
        }
        // no trailing barrier: next iteration writes the OTHER smem stage
    }
}

extern "C" void kernel_launch(void* const* d_in, const int* in_sizes, int n_in,
                              void* d_out, int out_size)
{
    // Resolve inputs by size, not position: img = 5,120,000 elems; rois = 1,200.
    const float* img;
    const int*   rois;
    if (in_sizes[0] > in_sizes[1]) {
        img  = (const float*)d_in[0];
        rois = (const int*)d_in[1];
    } else {
        img  = (const float*)d_in[1];
        rois = (const int*)d_in[0];
    }
    float* out = (float*)d_out;

    roi_pool_kernel<<<GRID_BLOCKS, 128>>>((const float2*)img, rois, (float2*)out);
}